// round 8
// baseline (speedup 1.0000x reference)
#include <cuda_runtime.h>
#include <math.h>

#define BB 64
#define CC 5
#define HH 50
#define LL 32
#define DD 300
#define QQ 200
#define VV 50000
#define NSLOT 55
#define MNEWS 2048           // BB*LL
#define MUSER 3200           // BB*HH
#define MTOT (NSLOT*MNEWS)   // 112640
#define PAD 132
#define SCAP 3200
#define NSL2 (NSLOT + 1)
#define JC 256
#define MAXCH 13
#define CPAD 304

typedef unsigned long long u64;

__device__ __forceinline__ u64 pack2(float x, float y) {
    u64 r; asm("mov.b64 %0, {%1, %2};" : "=l"(r) : "f"(x), "f"(y)); return r;
}
__device__ __forceinline__ void fma2(u64& d, u64 a, u64 b) {
    asm("fma.rn.f32x2 %0, %1, %2, %0;" : "+l"(d) : "l"(a), "l"(b));
}
__device__ __forceinline__ float2 unpack2(u64 v) {
    float2 f; asm("mov.b64 {%0, %1}, %2;" : "=f"(f.x), "=f"(f.y) : "l"(v)); return f;
}

// ---------------- static scratch ----------------
__device__ float d_V[(size_t)MTOT * DD];     // GAT output G (news)
__device__ float d_Wh[(size_t)MTOT * DD];    // embW: vocab @ news_W (first 50000*300 used)
__device__ float d_sv[MTOT];                 // vocab s (first VV used)
__device__ float d_tv[MTOT];                 // vocab t
__device__ int   d_tok[MTOT];                // per (slot,row) token
__device__ float d_enc[(size_t)NSLOT * BB * DD];
__device__ float d_uV[(size_t)MUSER * DD];
__device__ float d_uWh[(size_t)MUSER * DD];
__device__ float d_us[MUSER];
__device__ float d_ut[MUSER];
__device__ float d_uG[(size_t)MUSER * DD];
__device__ float d_user[(size_t)BB * DD];

// sorted per-slot arrays
__device__ float g_ts [(size_t)NSL2 * SCAP];
__device__ float g_E1 [(size_t)NSL2 * SCAP];
__device__ float g_E2 [(size_t)NSL2 * SCAP];
__device__ int   g_ti [(size_t)NSL2 * SCAP];  // W-row index (token for news, row for user)
__device__ float g_thr[(size_t)NSL2 * SCAP];
__device__ float g_es1[(size_t)NSL2 * SCAP];
__device__ float g_es2[(size_t)NSL2 * SCAP];
__device__ int   g_si [(size_t)NSL2 * SCAP];

// chunk partials
__device__ float g_cp1[(size_t)NSL2 * MAXCH * CPAD];
__device__ float g_cp2[(size_t)NSL2 * MAXCH * CPAD];
__device__ float g_cc1[NSL2 * MAXCH];
__device__ float g_cc2[NSL2 * MAXCH];

// additive-attention scratch
__device__ float g_score[MTOT];
__device__ float g_uscore[MUSER];
__device__ float g_lwTn[DD * QQ];
__device__ float g_lwTu[DD * QQ];

// ---------------- init scores ----------------
__global__ void init_kernel() {
    int i = blockIdx.x * 256 + threadIdx.x;
    if (i < MTOT) g_score[i] = 0.f;
    if (i < MUSER) g_uscore[i] = 0.f;
}

// ---------------- token map ----------------
__global__ void tok_kernel(const int* __restrict__ cand, const int* __restrict__ clicked) {
    int idx = blockIdx.x * 256 + threadIdx.x;
    if (idx >= MTOT) return;
    int slot = idx / MNEWS;
    int r    = idx - slot * MNEWS;
    int b = r >> 5, l = r & 31;
    int tok = (slot < CC) ? cand[(b * CC + slot) * LL + l]
                          : clicked[(b * HH + (slot - CC)) * LL + l];
    d_tok[idx] = min(max(tok, 0), VV - 1);
}

// ---------------- transpose lin_w [Q,D] -> [D,Q] ----------------
__global__ void transpose_kernel(const float* __restrict__ lw, float* __restrict__ lwT) {
    int idx = blockIdx.x * 256 + threadIdx.x;
    if (idx >= DD * QQ) return;
    int d = idx / QQ, q = idx - d * QQ;
    lwT[idx] = lw[q * DD + d];
}

// ---------------- SGEMM 128x128, 8x8/thread, f32x2 (M-guarded) ----------------
__global__ void __launch_bounds__(256, 2)
gemm_kernel(const float* __restrict__ A, const float* __restrict__ Bm,
            float* __restrict__ Cm, int M) {
    __shared__ __align__(16) float As[32][PAD];
    __shared__ __align__(16) float Bs[32][PAD];
    int nBase = blockIdx.x * 128;
    int mBase = blockIdx.y * 128;
    int tid = threadIdx.x;
    int ti = tid >> 4, td = tid & 15;
    int bj = tid >> 3, bc = (tid & 7) * 16;

    u64 acc[8][4];
#pragma unroll
    for (int r = 0; r < 8; r++)
#pragma unroll
        for (int c = 0; c < 4; c++) acc[r][c] = 0ull;

    for (int kt = 0; kt < DD; kt += 32) {
#pragma unroll
        for (int rr = 0; rr < 4; rr++) {
            int idx = tid + 256 * rr;
            int arow = idx >> 3;
            int acol = idx & 7;
            float4 v = make_float4(0.f, 0.f, 0.f, 0.f);
            if ((mBase + arow) < M && kt + acol * 4 + 3 < DD)
                v = *(const float4*)&A[(size_t)(mBase + arow) * DD + kt + acol * 4];
            As[acol * 4 + 0][arow] = v.x;
            As[acol * 4 + 1][arow] = v.y;
            As[acol * 4 + 2][arow] = v.z;
            As[acol * 4 + 3][arow] = v.w;
        }
        {
            bool rok = (kt + bj) < DD;
#pragma unroll
            for (int q = 0; q < 4; q++) {
                int col = bc + q * 4;
                float4 v = make_float4(0.f, 0.f, 0.f, 0.f);
                if (rok && (nBase + col + 3) < DD)
                    v = *(const float4*)&Bm[(size_t)(kt + bj) * DD + nBase + col];
                *(float4*)&Bs[bj][col] = v;
            }
        }
        __syncthreads();
#pragma unroll
        for (int kk = 0; kk < 32; kk++) {
            float4 aA = *(const float4*)&As[kk][ti * 8];
            float4 aB = *(const float4*)&As[kk][ti * 8 + 4];
            const u64* bp = (const u64*)&Bs[kk][td * 8];
            u64 b0 = bp[0], b1 = bp[1], b2 = bp[2], b3 = bp[3];
            float av[8] = {aA.x, aA.y, aA.z, aA.w, aB.x, aB.y, aB.z, aB.w};
#pragma unroll
            for (int r = 0; r < 8; r++) {
                u64 ap = pack2(av[r], av[r]);
                fma2(acc[r][0], ap, b0);
                fma2(acc[r][1], ap, b1);
                fma2(acc[r][2], ap, b2);
                fma2(acc[r][3], ap, b3);
            }
        }
        __syncthreads();
    }
    int col0 = nBase + td * 8;
#pragma unroll
    for (int r = 0; r < 8; r++) {
        int mrow = mBase + ti * 8 + r;
        if (mrow >= M) continue;
        float* crow = Cm + (size_t)mrow * DD;
        float o[8];
#pragma unroll
        for (int c = 0; c < 4; c++) {
            float2 v = unpack2(acc[r][c]);
            o[2 * c] = v.x; o[2 * c + 1] = v.y;
        }
        if (col0 + 7 < DD) {
            *(float4*)&crow[col0]     = make_float4(o[0], o[1], o[2], o[3]);
            *(float4*)&crow[col0 + 4] = make_float4(o[4], o[5], o[6], o[7]);
        } else {
#pragma unroll
            for (int e = 0; e < 8; e++)
                if (col0 + e < DD) crow[col0 + e] = o[e];
        }
    }
}

// ---------------- score GEMM ----------------
__global__ void __launch_bounds__(256, 2)
score_gemm_kernel(const float* __restrict__ A, const float* __restrict__ Bt,
                  const float* __restrict__ lin_b, const float* __restrict__ query,
                  float* __restrict__ score) {
    __shared__ __align__(16) float As[32][PAD];
    __shared__ __align__(16) float Bs[32][PAD];
    __shared__ float ssum[128];
    int nBase = blockIdx.x * 128;
    int mBase = blockIdx.y * 128;
    int tid = threadIdx.x;
    int ti = tid >> 4, td = tid & 15;
    int bj = tid >> 3, bc = (tid & 7) * 16;

    u64 acc[8][4];
#pragma unroll
    for (int r = 0; r < 8; r++)
#pragma unroll
        for (int c = 0; c < 4; c++) acc[r][c] = 0ull;

    for (int kt = 0; kt < DD; kt += 32) {
#pragma unroll
        for (int rr = 0; rr < 4; rr++) {
            int idx = tid + 256 * rr;
            int arow = idx >> 3;
            int acol = idx & 7;
            float4 v = make_float4(0.f, 0.f, 0.f, 0.f);
            if (kt + acol * 4 + 3 < DD)
                v = *(const float4*)&A[(size_t)(mBase + arow) * DD + kt + acol * 4];
            As[acol * 4 + 0][arow] = v.x;
            As[acol * 4 + 1][arow] = v.y;
            As[acol * 4 + 2][arow] = v.z;
            As[acol * 4 + 3][arow] = v.w;
        }
        {
            bool rok = (kt + bj) < DD;
#pragma unroll
            for (int q = 0; q < 4; q++) {
                int col = bc + q * 4;
                float4 v = make_float4(0.f, 0.f, 0.f, 0.f);
                if (rok && (nBase + col + 3) < QQ)
                    v = *(const float4*)&Bt[(size_t)(kt + bj) * QQ + nBase + col];
                *(float4*)&Bs[bj][col] = v;
            }
        }
        __syncthreads();
#pragma unroll
        for (int kk = 0; kk < 32; kk++) {
            float4 aA = *(const float4*)&As[kk][ti * 8];
            float4 aB = *(const float4*)&As[kk][ti * 8 + 4];
            const u64* bp = (const u64*)&Bs[kk][td * 8];
            u64 b0 = bp[0], b1 = bp[1], b2 = bp[2], b3 = bp[3];
            float av[8] = {aA.x, aA.y, aA.z, aA.w, aB.x, aB.y, aB.z, aB.w};
#pragma unroll
            for (int r = 0; r < 8; r++) {
                u64 ap = pack2(av[r], av[r]);
                fma2(acc[r][0], ap, b0);
                fma2(acc[r][1], ap, b1);
                fma2(acc[r][2], ap, b2);
                fma2(acc[r][3], ap, b3);
            }
        }
        __syncthreads();
    }

    if (tid < 128) ssum[tid] = 0.f;
    __syncthreads();

    int col0 = nBase + td * 8;
#pragma unroll
    for (int r = 0; r < 8; r++) {
        float o[8];
#pragma unroll
        for (int c = 0; c < 4; c++) {
            float2 v = unpack2(acc[r][c]);
            o[2 * c] = v.x; o[2 * c + 1] = v.y;
        }
        float rs = 0.f;
#pragma unroll
        for (int e = 0; e < 8; e++) {
            int col = col0 + e;
            if (col < QQ) rs += tanhf(o[e] + lin_b[col]) * query[col];
        }
        atomicAdd(&ssum[ti * 8 + r], rs);
    }
    __syncthreads();
    if (tid < 128) atomicAdd(&score[mBase + tid], ssum[tid]);
}

// ---------------- s,t per row ----------------
__global__ void st_kernel(const float* __restrict__ Wh, const float* __restrict__ a,
                          float* __restrict__ sv, float* __restrict__ tv, int M) {
    int row  = blockIdx.x * 8 + (threadIdx.x >> 5);
    int lane = threadIdx.x & 31;
    if (row >= M) return;
    const float* w = Wh + (size_t)row * DD;
    float s = 0.f, t = 0.f;
    for (int c = lane; c < DD; c += 32) {
        float v = w[c];
        s += v * a[c];
        t += v * a[DD + c];
    }
#pragma unroll
    for (int o = 16; o; o >>= 1) {
        s += __shfl_xor_sync(0xffffffffu, s, o);
        t += __shfl_xor_sync(0xffffffffu, t, o);
    }
    if (!lane) { sv[row] = s; tv[row] = t; }
}

// ---------------- bitonic sort (templated size) ----------------
template<int NS>
__device__ void bitonicNS(float* key, int* val) {
    for (int k = 2; k <= NS; k <<= 1) {
        for (int j = k >> 1; j > 0; j >>= 1) {
            for (int t = threadIdx.x; t < NS / 2; t += blockDim.x) {
                int i = 2 * t - (t & (j - 1));
                int l = i + j;
                bool up = ((i & k) == 0);
                float ki = key[i], kl = key[l];
                if (up ? (ki > kl) : (ki < kl)) {
                    key[i] = kl; key[l] = ki;
                    int vi = val[i]; val[i] = val[l]; val[l] = vi;
                }
            }
            __syncthreads();
        }
    }
}

// tok != null: tv/sv are vocab arrays, indexed via tok[blockIdx.x*M + i]
template<int NS>
__global__ void __launch_bounds__(1024)
sort_kernel(const float* __restrict__ tv, const float* __restrict__ sv,
            const int* __restrict__ tok, int M, int slotBase) {
    __shared__ float key[NS];
    __shared__ int   val[NS];
    int slot = slotBase + blockIdx.x;
    size_t sb = (size_t)slot * SCAP;
    const int* tk = tok ? (tok + (size_t)blockIdx.x * M) : 0;

    for (int i = threadIdx.x; i < NS; i += blockDim.x) {
        key[i] = (i < M) ? (tk ? tv[tk[i]] : tv[(size_t)blockIdx.x * M + i]) : 3.0e38f;
        val[i] = i;
    }
    __syncthreads();
    bitonicNS<NS>(key, val);
    for (int i = threadIdx.x; i < M; i += blockDim.x) {
        float k = key[i];
        int r = val[i];
        g_ts[sb + i] = k;
        g_ti[sb + i] = tk ? tk[r] : r;            // W-row (token for news)
        g_E1[sb + i] = __expf(k);
        g_E2[sb + i] = __expf(0.2f * k);
    }
    __syncthreads();

    for (int i = threadIdx.x; i < NS; i += blockDim.x) {
        key[i] = (i < M) ? (tk ? -sv[tk[i]] : -sv[(size_t)blockIdx.x * M + i]) : 3.0e38f;
        val[i] = i;
    }
    __syncthreads();
    bitonicNS<NS>(key, val);
    for (int i = threadIdx.x; i < M; i += blockDim.x) {
        float k = key[i];
        g_thr[sb + i] = k;
        g_si [sb + i] = val[i];
        g_es1[sb + i] = __expf(-k);
        g_es2[sb + i] = __expf(-0.2f * k);
    }
}

// ---------------- phase A: per-chunk partial sums ----------------
__global__ void __launch_bounds__(320)
partials_kernel(const float* __restrict__ Wbase, size_t wStride, int M, int slotBase) {
    int slot = slotBase + blockIdx.y;
    size_t sb = (size_t)slot * SCAP;
    const float* W = Wbase + (size_t)blockIdx.y * wStride;
    int ch = blockIdx.x;
    int jstart = ch * JC, jend = min(M, jstart + JC);
    int t = threadIdx.x;

    if (t < DD) {
        int d = t;
        float p1 = 0.f, p2 = 0.f;
        float wb[4];
#pragma unroll
        for (int q = 0; q < 4; q++) wb[q] = W[(size_t)g_ti[sb + jstart + q] * DD + d];
        for (int jb = jstart; jb < jend; jb += 4) {
            float wn[4] = {0.f, 0.f, 0.f, 0.f};
            if (jb + 4 < jend) {
#pragma unroll
                for (int q = 0; q < 4; q++)
                    wn[q] = W[(size_t)g_ti[sb + jb + 4 + q] * DD + d];
            }
#pragma unroll
            for (int q = 0; q < 4; q++) {
                float e1 = g_E1[sb + jb + q], e2 = g_E2[sb + jb + q];
                p1 += e1 * wb[q]; p2 += e2 * wb[q];
            }
#pragma unroll
            for (int q = 0; q < 4; q++) wb[q] = wn[q];
        }
        size_t o = (size_t)(slot * MAXCH + ch) * CPAD + d;
        g_cp1[o] = p1; g_cp2[o] = p2;
    } else if (t == DD) {
        float c = 0.f;
        for (int j = jstart; j < jend; j++) c += g_E1[sb + j];
        g_cc1[slot * MAXCH + ch] = c;
    } else if (t == DD + 1) {
        float c = 0.f;
        for (int j = jstart; j < jend; j++) c += g_E2[sb + j];
        g_cc2[slot * MAXCH + ch] = c;
    }
}

// ---------------- phase C: per-chunk merge sweep ----------------
__global__ void __launch_bounds__(320)
csweep_kernel(const float* __restrict__ Wbase, size_t wStride, float* __restrict__ G_all,
              int M, int slotBase, int nch) {
    __shared__ float ts[JC], e1s[JC], e2s[JC];
    __shared__ int tis[JC];
    int slot = slotBase + blockIdx.y;
    size_t sb = (size_t)slot * SCAP;
    const float* W = Wbase + (size_t)blockIdx.y * wStride;
    float* G = G_all + (size_t)blockIdx.y * M * DD;
    int ch = blockIdx.x;
    int jstart = ch * JC, jend = min(M, jstart + JC);
    int jn = jend - jstart;

    for (int i = threadIdx.x; i < jn; i += blockDim.x) {
        ts[i]  = g_ts[sb + jstart + i];
        e1s[i] = g_E1[sb + jstart + i];
        e2s[i] = g_E2[sb + jstart + i];
        tis[i] = g_ti[sb + jstart + i];
    }
    __syncthreads();

    int t = threadIdx.x;
    bool act = t < DD;
    int d = act ? t : DD - 1;

    float p1 = 0.f, p2 = 0.f, c1 = 0.f, c2 = 0.f, T1 = 0.f, C1 = 0.f;
    int base = slot * MAXCH;
    for (int k = 0; k < nch; k++) {
        float v1 = g_cp1[(size_t)(base + k) * CPAD + d];
        float s1 = g_cc1[base + k];
        T1 += v1; C1 += s1;
        if (k < ch) {
            p1 += v1; c1 += s1;
            p2 += g_cp2[(size_t)(base + k) * CPAD + d];
            c2 += g_cc2[base + k];
        }
    }

    float tPrev = (jstart == 0) ? -3.4e38f : g_ts[sb + jstart - 1];
    int lo = 0, hi = M;
    while (lo < hi) { int mid = (lo + hi) >> 1; if (g_thr[sb + mid] <= tPrev) lo = mid + 1; else hi = mid; }
    int ptr = lo;
    int r1 = M;
    if (jend < M) {
        float tLast = ts[jn - 1];
        lo = 0; hi = M;
        while (lo < hi) { int mid = (lo + hi) >> 1; if (g_thr[sb + mid] <= tLast) lo = mid + 1; else hi = mid; }
        r1 = lo;
    }

    float wb[4];
#pragma unroll
    for (int q = 0; q < 4; q++) wb[q] = W[(size_t)tis[q] * DD + d];

    for (int jb = 0; jb < jn; jb += 4) {
        float wn[4] = {0.f, 0.f, 0.f, 0.f};
        if (jb + 4 < jn) {
#pragma unroll
            for (int q = 0; q < 4; q++) wn[q] = W[(size_t)tis[jb + 4 + q] * DD + d];
        }
#pragma unroll
        for (int q = 0; q < 4; q++) {
            float tj = ts[jb + q];
            while (ptr < r1 && g_thr[sb + ptr] <= tj) {
                float a1 = g_es1[sb + ptr], a2 = g_es2[sb + ptr];
                int si = g_si[sb + ptr];
                float den = a1 * (C1 - c1) + a2 * c2;
                float v = __fdividef(a1 * (T1 - p1) + a2 * p2, den);
                v = (v > 0.f) ? v : (__expf(v) - 1.f);
                if (act) G[(size_t)si * DD + d] = v;
                ptr++;
            }
            float e1 = e1s[jb + q], e2 = e2s[jb + q];
            p1 += e1 * wb[q]; p2 += e2 * wb[q];
            c1 += e1; c2 += e2;
        }
#pragma unroll
        for (int q = 0; q < 4; q++) wb[q] = wn[q];
    }
    while (ptr < r1) {
        float a1 = g_es1[sb + ptr], a2 = g_es2[sb + ptr];
        int si = g_si[sb + ptr];
        float den = a1 * (C1 - c1) + a2 * c2;
        float v = __fdividef(a1 * (T1 - p1) + a2 * p2, den);
        v = (v > 0.f) ? v : (__expf(v) - 1.f);
        if (act) G[(size_t)si * DD + d] = v;
        ptr++;
    }
}

// ---------------- softmax + weighted sum ----------------
__global__ void softsum_kernel(const float* __restrict__ X, const float* __restrict__ sc,
                               int S, int slotM, float* __restrict__ outB) {
    __shared__ float wsm[64];
    int b = blockIdx.x, slot = blockIdx.y;
    int rowBase = slot * slotM + b * S;
    int lane = threadIdx.x;
    if (threadIdx.x < 32) {
        float v0 = (lane < S) ? sc[rowBase + lane] : -1e30f;
        float v1 = ((lane + 32) < S) ? sc[rowBase + lane + 32] : -1e30f;
        float m = fmaxf(v0, v1);
#pragma unroll
        for (int o = 16; o; o >>= 1) m = fmaxf(m, __shfl_xor_sync(0xffffffffu, m, o));
        float e0 = (lane < S) ? __expf(v0 - m) : 0.f;
        float e1 = ((lane + 32) < S) ? __expf(v1 - m) : 0.f;
        float sum = e0 + e1;
#pragma unroll
        for (int o = 16; o; o >>= 1) sum += __shfl_xor_sync(0xffffffffu, sum, o);
        float inv = 1.f / sum;
        wsm[lane] = e0 * inv;
        wsm[lane + 32] = e1 * inv;
    }
    __syncthreads();
    float* o = outB + (size_t)(slot * BB + b) * DD;
    for (int dd = threadIdx.x; dd < DD; dd += blockDim.x) {
        float acc = 0.f;
        for (int s = 0; s < S; s++)
            acc += wsm[s] * X[(size_t)(rowBase + s) * DD + dd];
        o[dd] = acc;
    }
}

// ---------------- reorder clicked encodings ----------------
__global__ void copy_uV_kernel() {
    int row  = blockIdx.x * 8 + (threadIdx.x >> 5);
    int lane = threadIdx.x & 31;
    if (row >= MUSER) return;
    int b = row / HH, j = row - b * HH;
    const float* src = d_enc + ((size_t)(CC + j) * BB + b) * DD;
    float* dst = d_uV + (size_t)row * DD;
    for (int c = lane; c < DD; c += 32) dst[c] = src[c];
}

// ---------------- final scores ----------------
__global__ void scores_kernel(float* __restrict__ out) {
    int w    = (blockIdx.x * blockDim.x + threadIdx.x) >> 5;
    int lane = threadIdx.x & 31;
    if (w >= BB * CC) return;
    int b = w / CC, c = w - b * CC;
    const float* cd = d_enc + ((size_t)c * BB + b) * DD;
    const float* u  = d_user + (size_t)b * DD;
    float acc = 0.f;
    for (int k = lane; k < DD; k += 32) acc += cd[k] * u[k];
#pragma unroll
    for (int o = 16; o; o >>= 1) acc += __shfl_xor_sync(0xffffffffu, acc, o);
    if (!lane) out[b * CC + c] = acc;
}

// ---------------- launch ----------------
extern "C" void kernel_launch(void* const* d_in, const int* in_sizes, int n_in,
                              void* d_out, int out_size) {
    const void* by200[4] = {0, 0, 0, 0};
    const void* by600[2] = {0, 0};
    const void* by60k[2] = {0, 0};
    const void* by90k[2] = {0, 0};
    const int* cand = 0; const int* clicked = 0; const float* emb = 0;
    int n200 = 0, n600 = 0, n60k = 0, n90k = 0;
    for (int i = 0; i < n_in; i++) {
        int sz = in_sizes[i];
        if      (sz == BB * CC * LL)      cand    = (const int*)d_in[i];
        else if (sz == BB * HH * LL)      clicked = (const int*)d_in[i];
        else if (sz == VV * DD)           emb     = (const float*)d_in[i];
        else if (sz == DD * DD  && n90k < 2) by90k[n90k++] = d_in[i];
        else if (sz == 2 * DD   && n600 < 2) by600[n600++] = d_in[i];
        else if (sz == QQ * DD  && n60k < 2) by60k[n60k++] = d_in[i];
        else if (sz == QQ       && n200 < 4) by200[n200++] = d_in[i];
    }
    const float* news_W     = (const float*)by90k[0];
    const float* user_W     = (const float*)by90k[1];
    const float* news_a     = (const float*)by600[0];
    const float* user_a     = (const float*)by600[1];
    const float* news_lin_w = (const float*)by60k[0];
    const float* user_lin_w = (const float*)by60k[1];
    const float* news_lin_b = (const float*)by200[0];
    const float* news_query = (const float*)by200[1];
    const float* user_lin_b = (const float*)by200[2];
    const float* user_query = (const float*)by200[3];
    float* out = (float*)d_out;

    float *pV, *pWh, *pS, *pT, *pEnc, *pUV, *pUWh, *pUS, *pUT, *pUG, *pUser;
    float *pScore, *pUScore, *pLwTn, *pLwTu;
    int *pTok;
    cudaGetSymbolAddress((void**)&pV, d_V);
    cudaGetSymbolAddress((void**)&pWh, d_Wh);
    cudaGetSymbolAddress((void**)&pS, d_sv);
    cudaGetSymbolAddress((void**)&pT, d_tv);
    cudaGetSymbolAddress((void**)&pTok, d_tok);
    cudaGetSymbolAddress((void**)&pEnc, d_enc);
    cudaGetSymbolAddress((void**)&pUV, d_uV);
    cudaGetSymbolAddress((void**)&pUWh, d_uWh);
    cudaGetSymbolAddress((void**)&pUS, d_us);
    cudaGetSymbolAddress((void**)&pUT, d_ut);
    cudaGetSymbolAddress((void**)&pUG, d_uG);
    cudaGetSymbolAddress((void**)&pUser, d_user);
    cudaGetSymbolAddress((void**)&pScore, g_score);
    cudaGetSymbolAddress((void**)&pUScore, g_uscore);
    cudaGetSymbolAddress((void**)&pLwTn, g_lwTn);
    cudaGetSymbolAddress((void**)&pLwTu, g_lwTu);

    const int NCH_NEWS = (MNEWS + JC - 1) / JC;   // 8
    const int NCH_USER = (MUSER + JC - 1) / JC;   // 13

    // prep
    init_kernel<<<(MTOT + 255) / 256, 256>>>();
    transpose_kernel<<<(DD * QQ + 255) / 256, 256>>>(news_lin_w, pLwTn);
    transpose_kernel<<<(DD * QQ + 255) / 256, 256>>>(user_lin_w, pLwTu);
    tok_kernel<<<(MTOT + 255) / 256, 256>>>(cand, clicked);

    // news pipeline (vocab-level Wh)
    gemm_kernel<<<dim3(3, (VV + 127) / 128), 256>>>(emb, news_W, pWh, VV);
    st_kernel<<<(VV + 7) / 8, 256>>>(pWh, news_a, pS, pT, VV);
    sort_kernel<2048><<<NSLOT, 1024>>>(pT, pS, pTok, MNEWS, 0);
    partials_kernel<<<dim3(NCH_NEWS, NSLOT), 320>>>(pWh, 0, MNEWS, 0);
    csweep_kernel<<<dim3(NCH_NEWS, NSLOT), 320>>>(pWh, 0, pV, MNEWS, 0, NCH_NEWS);
    score_gemm_kernel<<<dim3(2, MTOT / 128), 256>>>(pV, pLwTn, news_lin_b, news_query, pScore);
    softsum_kernel<<<dim3(BB, NSLOT), 128>>>(pV, pScore, LL, MNEWS, pEnc);

    // user pipeline
    copy_uV_kernel<<<MUSER / 8, 256>>>();
    gemm_kernel<<<dim3(3, MUSER / 128), 256>>>(pUV, user_W, pUWh, MUSER);
    st_kernel<<<MUSER / 8, 256>>>(pUWh, user_a, pUS, pUT, MUSER);
    sort_kernel<4096><<<1, 1024>>>(pUT, pUS, 0, MUSER, NSLOT);
    partials_kernel<<<dim3(NCH_USER, 1), 320>>>(pUWh, 0, MUSER, NSLOT);
    csweep_kernel<<<dim3(NCH_USER, 1), 320>>>(pUWh, 0, pUG, MUSER, NSLOT, NCH_USER);
    score_gemm_kernel<<<dim3(2, MUSER / 128), 256>>>(pUG, pLwTu, user_lin_b, user_query, pUScore);
    softsum_kernel<<<dim3(BB, 1), 128>>>(pUG, pUScore, HH, MUSER, pUser);

    scores_kernel<<<40, 256>>>(out);
}

// round 9
// speedup vs baseline: 1.5329x; 1.5329x over previous
#include <cuda_runtime.h>
#include <math.h>

#define BB 64
#define CC 5
#define HH 50
#define LL 32
#define DD 300
#define QQ 200
#define VV 50000
#define NSLOT 55
#define MNEWS 2048           // BB*LL
#define MUSER 3200           // BB*HH
#define MTOT (NSLOT*MNEWS)   // 112640
#define PAD 132
#define SCAP 3200
#define NSL2 (NSLOT + 1)
#define JC 256
#define MAXCH 13
#define CPAD 304

typedef unsigned long long u64;

__device__ __forceinline__ u64 pack2(float x, float y) {
    u64 r; asm("mov.b64 %0, {%1, %2};" : "=l"(r) : "f"(x), "f"(y)); return r;
}
__device__ __forceinline__ void fma2(u64& d, u64 a, u64 b) {
    asm("fma.rn.f32x2 %0, %1, %2, %0;" : "+l"(d) : "l"(a), "l"(b));
}
__device__ __forceinline__ float2 unpack2(u64 v) {
    float2 f; asm("mov.b64 {%0, %1}, %2;" : "=f"(f.x), "=f"(f.y) : "l"(v)); return f;
}

// ---------------- static scratch ----------------
__device__ float d_embW[(size_t)VV * DD];    // vocab @ news_W
__device__ float d_vs[VV];                   // vocab s
__device__ float d_vt[VV];                   // vocab t
__device__ float d_V[(size_t)MTOT * DD];     // GAT output G (news)
__device__ float d_Wh[(size_t)MTOT * DD];    // per-slot contiguous Wh
__device__ float d_sv[MTOT];
__device__ float d_tv[MTOT];
__device__ float d_enc[(size_t)NSLOT * BB * DD];
__device__ float d_uV[(size_t)MUSER * DD];
__device__ float d_uWh[(size_t)MUSER * DD];
__device__ float d_us[MUSER];
__device__ float d_ut[MUSER];
__device__ float d_uG[(size_t)MUSER * DD];
__device__ float d_user[(size_t)BB * DD];

// sorted per-slot arrays (local row indices)
__device__ float g_ts [(size_t)NSL2 * SCAP];
__device__ float g_E1 [(size_t)NSL2 * SCAP];
__device__ float g_E2 [(size_t)NSL2 * SCAP];
__device__ int   g_ti [(size_t)NSL2 * SCAP];
__device__ float g_thr[(size_t)NSL2 * SCAP];
__device__ float g_es1[(size_t)NSL2 * SCAP];
__device__ float g_es2[(size_t)NSL2 * SCAP];
__device__ int   g_si [(size_t)NSL2 * SCAP];

// chunk partials
__device__ float g_cp1[(size_t)NSL2 * MAXCH * CPAD];
__device__ float g_cp2[(size_t)NSL2 * MAXCH * CPAD];
__device__ float g_cc1[NSL2 * MAXCH];
__device__ float g_cc2[NSL2 * MAXCH];

// additive-attention scratch
__device__ float g_score[MTOT];
__device__ float g_uscore[MUSER];
__device__ float g_lwTn[DD * QQ];
__device__ float g_lwTu[DD * QQ];

// ---------------- init scores ----------------
__global__ void init_kernel() {
    int i = blockIdx.x * 256 + threadIdx.x;
    if (i < MTOT) g_score[i] = 0.f;
    if (i < MUSER) g_uscore[i] = 0.f;
}

// ---------------- transpose lin_w [Q,D] -> [D,Q] ----------------
__global__ void transpose_kernel(const float* __restrict__ lw, float* __restrict__ lwT) {
    int idx = blockIdx.x * 256 + threadIdx.x;
    if (idx >= DD * QQ) return;
    int d = idx / QQ, q = idx - d * QQ;
    lwT[idx] = lw[q * DD + d];
}

// ---------------- gather Wh rows (+ per-row s,t) from vocab-level results ----------
__global__ void gatherWh_kernel(const int* __restrict__ cand,
                                const int* __restrict__ clicked) {
    int row  = blockIdx.x * 8 + (threadIdx.x >> 5);
    int lane = threadIdx.x & 31;
    if (row >= MTOT) return;
    int slot = row / MNEWS;
    int r    = row - slot * MNEWS;
    int b = r >> 5, l = r & 31;
    int tok = (slot < CC) ? cand[(b * CC + slot) * LL + l]
                          : clicked[(b * HH + (slot - CC)) * LL + l];
    tok = min(max(tok, 0), VV - 1);
    const float2* src = (const float2*)(d_embW + (size_t)tok * DD);
    float2* dst = (float2*)(d_Wh + (size_t)row * DD);
    for (int c = lane; c < DD / 2; c += 32) dst[c] = src[c];
    if (!lane) { d_sv[row] = d_vs[tok]; d_tv[row] = d_vt[tok]; }
}

// ---------------- SGEMM 128x128, 8x8/thread, f32x2 (M-guarded) ----------------
__global__ void __launch_bounds__(256, 2)
gemm_kernel(const float* __restrict__ A, const float* __restrict__ Bm,
            float* __restrict__ Cm, int M) {
    __shared__ __align__(16) float As[32][PAD];
    __shared__ __align__(16) float Bs[32][PAD];
    int nBase = blockIdx.x * 128;
    int mBase = blockIdx.y * 128;
    int tid = threadIdx.x;
    int ti = tid >> 4, td = tid & 15;
    int bj = tid >> 3, bc = (tid & 7) * 16;

    u64 acc[8][4];
#pragma unroll
    for (int r = 0; r < 8; r++)
#pragma unroll
        for (int c = 0; c < 4; c++) acc[r][c] = 0ull;

    for (int kt = 0; kt < DD; kt += 32) {
#pragma unroll
        for (int rr = 0; rr < 4; rr++) {
            int idx = tid + 256 * rr;
            int arow = idx >> 3;
            int acol = idx & 7;
            float4 v = make_float4(0.f, 0.f, 0.f, 0.f);
            if ((mBase + arow) < M && kt + acol * 4 + 3 < DD)
                v = *(const float4*)&A[(size_t)(mBase + arow) * DD + kt + acol * 4];
            As[acol * 4 + 0][arow] = v.x;
            As[acol * 4 + 1][arow] = v.y;
            As[acol * 4 + 2][arow] = v.z;
            As[acol * 4 + 3][arow] = v.w;
        }
        {
            bool rok = (kt + bj) < DD;
#pragma unroll
            for (int q = 0; q < 4; q++) {
                int col = bc + q * 4;
                float4 v = make_float4(0.f, 0.f, 0.f, 0.f);
                if (rok && (nBase + col + 3) < DD)
                    v = *(const float4*)&Bm[(size_t)(kt + bj) * DD + nBase + col];
                *(float4*)&Bs[bj][col] = v;
            }
        }
        __syncthreads();
#pragma unroll
        for (int kk = 0; kk < 32; kk++) {
            float4 aA = *(const float4*)&As[kk][ti * 8];
            float4 aB = *(const float4*)&As[kk][ti * 8 + 4];
            const u64* bp = (const u64*)&Bs[kk][td * 8];
            u64 b0 = bp[0], b1 = bp[1], b2 = bp[2], b3 = bp[3];
            float av[8] = {aA.x, aA.y, aA.z, aA.w, aB.x, aB.y, aB.z, aB.w};
#pragma unroll
            for (int r = 0; r < 8; r++) {
                u64 ap = pack2(av[r], av[r]);
                fma2(acc[r][0], ap, b0);
                fma2(acc[r][1], ap, b1);
                fma2(acc[r][2], ap, b2);
                fma2(acc[r][3], ap, b3);
            }
        }
        __syncthreads();
    }
    int col0 = nBase + td * 8;
#pragma unroll
    for (int r = 0; r < 8; r++) {
        int mrow = mBase + ti * 8 + r;
        if (mrow >= M) continue;
        float* crow = Cm + (size_t)mrow * DD;
        float o[8];
#pragma unroll
        for (int c = 0; c < 4; c++) {
            float2 v = unpack2(acc[r][c]);
            o[2 * c] = v.x; o[2 * c + 1] = v.y;
        }
        if (col0 + 7 < DD) {
            *(float4*)&crow[col0]     = make_float4(o[0], o[1], o[2], o[3]);
            *(float4*)&crow[col0 + 4] = make_float4(o[4], o[5], o[6], o[7]);
        } else {
#pragma unroll
            for (int e = 0; e < 8; e++)
                if (col0 + e < DD) crow[col0 + e] = o[e];
        }
    }
}

// ---------------- score GEMM ----------------
__global__ void __launch_bounds__(256, 2)
score_gemm_kernel(const float* __restrict__ A, const float* __restrict__ Bt,
                  const float* __restrict__ lin_b, const float* __restrict__ query,
                  float* __restrict__ score) {
    __shared__ __align__(16) float As[32][PAD];
    __shared__ __align__(16) float Bs[32][PAD];
    __shared__ float ssum[128];
    int nBase = blockIdx.x * 128;
    int mBase = blockIdx.y * 128;
    int tid = threadIdx.x;
    int ti = tid >> 4, td = tid & 15;
    int bj = tid >> 3, bc = (tid & 7) * 16;

    u64 acc[8][4];
#pragma unroll
    for (int r = 0; r < 8; r++)
#pragma unroll
        for (int c = 0; c < 4; c++) acc[r][c] = 0ull;

    for (int kt = 0; kt < DD; kt += 32) {
#pragma unroll
        for (int rr = 0; rr < 4; rr++) {
            int idx = tid + 256 * rr;
            int arow = idx >> 3;
            int acol = idx & 7;
            float4 v = make_float4(0.f, 0.f, 0.f, 0.f);
            if (kt + acol * 4 + 3 < DD)
                v = *(const float4*)&A[(size_t)(mBase + arow) * DD + kt + acol * 4];
            As[acol * 4 + 0][arow] = v.x;
            As[acol * 4 + 1][arow] = v.y;
            As[acol * 4 + 2][arow] = v.z;
            As[acol * 4 + 3][arow] = v.w;
        }
        {
            bool rok = (kt + bj) < DD;
#pragma unroll
            for (int q = 0; q < 4; q++) {
                int col = bc + q * 4;
                float4 v = make_float4(0.f, 0.f, 0.f, 0.f);
                if (rok && (nBase + col + 3) < QQ)
                    v = *(const float4*)&Bt[(size_t)(kt + bj) * QQ + nBase + col];
                *(float4*)&Bs[bj][col] = v;
            }
        }
        __syncthreads();
#pragma unroll
        for (int kk = 0; kk < 32; kk++) {
            float4 aA = *(const float4*)&As[kk][ti * 8];
            float4 aB = *(const float4*)&As[kk][ti * 8 + 4];
            const u64* bp = (const u64*)&Bs[kk][td * 8];
            u64 b0 = bp[0], b1 = bp[1], b2 = bp[2], b3 = bp[3];
            float av[8] = {aA.x, aA.y, aA.z, aA.w, aB.x, aB.y, aB.z, aB.w};
#pragma unroll
            for (int r = 0; r < 8; r++) {
                u64 ap = pack2(av[r], av[r]);
                fma2(acc[r][0], ap, b0);
                fma2(acc[r][1], ap, b1);
                fma2(acc[r][2], ap, b2);
                fma2(acc[r][3], ap, b3);
            }
        }
        __syncthreads();
    }

    if (tid < 128) ssum[tid] = 0.f;
    __syncthreads();

    int col0 = nBase + td * 8;
#pragma unroll
    for (int r = 0; r < 8; r++) {
        float o[8];
#pragma unroll
        for (int c = 0; c < 4; c++) {
            float2 v = unpack2(acc[r][c]);
            o[2 * c] = v.x; o[2 * c + 1] = v.y;
        }
        float rs = 0.f;
#pragma unroll
        for (int e = 0; e < 8; e++) {
            int col = col0 + e;
            if (col < QQ) rs += tanhf(o[e] + lin_b[col]) * query[col];
        }
        atomicAdd(&ssum[ti * 8 + r], rs);
    }
    __syncthreads();
    if (tid < 128) atomicAdd(&score[mBase + tid], ssum[tid]);
}

// ---------------- s,t per row ----------------
__global__ void st_kernel(const float* __restrict__ Wh, const float* __restrict__ a,
                          float* __restrict__ sv, float* __restrict__ tv, int M) {
    int row  = blockIdx.x * 8 + (threadIdx.x >> 5);
    int lane = threadIdx.x & 31;
    if (row >= M) return;
    const float* w = Wh + (size_t)row * DD;
    float s = 0.f, t = 0.f;
    for (int c = lane; c < DD; c += 32) {
        float v = w[c];
        s += v * a[c];
        t += v * a[DD + c];
    }
#pragma unroll
    for (int o = 16; o; o >>= 1) {
        s += __shfl_xor_sync(0xffffffffu, s, o);
        t += __shfl_xor_sync(0xffffffffu, t, o);
    }
    if (!lane) { sv[row] = s; tv[row] = t; }
}

// ---------------- bitonic sort (templated size) ----------------
template<int NS>
__device__ void bitonicNS(float* key, int* val) {
    for (int k = 2; k <= NS; k <<= 1) {
        for (int j = k >> 1; j > 0; j >>= 1) {
            for (int t = threadIdx.x; t < NS / 2; t += blockDim.x) {
                int i = 2 * t - (t & (j - 1));
                int l = i + j;
                bool up = ((i & k) == 0);
                float ki = key[i], kl = key[l];
                if (up ? (ki > kl) : (ki < kl)) {
                    key[i] = kl; key[l] = ki;
                    int vi = val[i]; val[i] = val[l]; val[l] = vi;
                }
            }
            __syncthreads();
        }
    }
}

template<int NS>
__global__ void __launch_bounds__(1024)
sort_kernel(const float* __restrict__ tv, const float* __restrict__ sv,
            int M, int slotBase) {
    __shared__ float key[NS];
    __shared__ int   val[NS];
    int slot = slotBase + blockIdx.x;
    size_t sb = (size_t)slot * SCAP;
    const float* t = tv + (size_t)blockIdx.x * M;
    const float* s = sv + (size_t)blockIdx.x * M;

    for (int i = threadIdx.x; i < NS; i += blockDim.x) {
        key[i] = (i < M) ? t[i] : 3.0e38f;
        val[i] = i;
    }
    __syncthreads();
    bitonicNS<NS>(key, val);
    for (int i = threadIdx.x; i < M; i += blockDim.x) {
        float k = key[i];
        g_ts[sb + i] = k;
        g_ti[sb + i] = val[i];
        g_E1[sb + i] = __expf(k);
        g_E2[sb + i] = __expf(0.2f * k);
    }
    __syncthreads();

    for (int i = threadIdx.x; i < NS; i += blockDim.x) {
        key[i] = (i < M) ? (-s[i]) : 3.0e38f;
        val[i] = i;
    }
    __syncthreads();
    bitonicNS<NS>(key, val);
    for (int i = threadIdx.x; i < M; i += blockDim.x) {
        float k = key[i];
        g_thr[sb + i] = k;
        g_si [sb + i] = val[i];
        g_es1[sb + i] = __expf(-k);
        g_es2[sb + i] = __expf(-0.2f * k);
    }
}

// ---------------- phase A: per-chunk partial sums ----------------
__global__ void __launch_bounds__(320)
partials_kernel(const float* __restrict__ Wbase, size_t wStride, int M, int slotBase) {
    int slot = slotBase + blockIdx.y;
    size_t sb = (size_t)slot * SCAP;
    const float* W = Wbase + (size_t)blockIdx.y * wStride;
    int ch = blockIdx.x;
    int jstart = ch * JC, jend = min(M, jstart + JC);
    int t = threadIdx.x;

    if (t < DD) {
        int d = t;
        float p1 = 0.f, p2 = 0.f;
        float wb[4];
#pragma unroll
        for (int q = 0; q < 4; q++) wb[q] = W[(size_t)g_ti[sb + jstart + q] * DD + d];
        for (int jb = jstart; jb < jend; jb += 4) {
            float wn[4] = {0.f, 0.f, 0.f, 0.f};
            if (jb + 4 < jend) {
#pragma unroll
                for (int q = 0; q < 4; q++)
                    wn[q] = W[(size_t)g_ti[sb + jb + 4 + q] * DD + d];
            }
#pragma unroll
            for (int q = 0; q < 4; q++) {
                float e1 = g_E1[sb + jb + q], e2 = g_E2[sb + jb + q];
                p1 += e1 * wb[q]; p2 += e2 * wb[q];
            }
#pragma unroll
            for (int q = 0; q < 4; q++) wb[q] = wn[q];
        }
        size_t o = (size_t)(slot * MAXCH + ch) * CPAD + d;
        g_cp1[o] = p1; g_cp2[o] = p2;
    } else if (t == DD) {
        float c = 0.f;
        for (int j = jstart; j < jend; j++) c += g_E1[sb + j];
        g_cc1[slot * MAXCH + ch] = c;
    } else if (t == DD + 1) {
        float c = 0.f;
        for (int j = jstart; j < jend; j++) c += g_E2[sb + j];
        g_cc2[slot * MAXCH + ch] = c;
    }
}

// ---------------- phase C: per-chunk merge sweep ----------------
__global__ void __launch_bounds__(320)
csweep_kernel(const float* __restrict__ Wbase, size_t wStride, float* __restrict__ G_all,
              int M, int slotBase, int nch) {
    __shared__ float ts[JC], e1s[JC], e2s[JC];
    __shared__ int tis[JC];
    int slot = slotBase + blockIdx.y;
    size_t sb = (size_t)slot * SCAP;
    const float* W = Wbase + (size_t)blockIdx.y * wStride;
    float* G = G_all + (size_t)blockIdx.y * M * DD;
    int ch = blockIdx.x;
    int jstart = ch * JC, jend = min(M, jstart + JC);
    int jn = jend - jstart;

    for (int i = threadIdx.x; i < jn; i += blockDim.x) {
        ts[i]  = g_ts[sb + jstart + i];
        e1s[i] = g_E1[sb + jstart + i];
        e2s[i] = g_E2[sb + jstart + i];
        tis[i] = g_ti[sb + jstart + i];
    }
    __syncthreads();

    int t = threadIdx.x;
    bool act = t < DD;
    int d = act ? t : DD - 1;

    float p1 = 0.f, p2 = 0.f, c1 = 0.f, c2 = 0.f, T1 = 0.f, C1 = 0.f;
    int base = slot * MAXCH;
    for (int k = 0; k < nch; k++) {
        float v1 = g_cp1[(size_t)(base + k) * CPAD + d];
        float s1 = g_cc1[base + k];
        T1 += v1; C1 += s1;
        if (k < ch) {
            p1 += v1; c1 += s1;
            p2 += g_cp2[(size_t)(base + k) * CPAD + d];
            c2 += g_cc2[base + k];
        }
    }

    float tPrev = (jstart == 0) ? -3.4e38f : g_ts[sb + jstart - 1];
    int lo = 0, hi = M;
    while (lo < hi) { int mid = (lo + hi) >> 1; if (g_thr[sb + mid] <= tPrev) lo = mid + 1; else hi = mid; }
    int ptr = lo;
    int r1 = M;
    if (jend < M) {
        float tLast = ts[jn - 1];
        lo = 0; hi = M;
        while (lo < hi) { int mid = (lo + hi) >> 1; if (g_thr[sb + mid] <= tLast) lo = mid + 1; else hi = mid; }
        r1 = lo;
    }

    float wb[4];
#pragma unroll
    for (int q = 0; q < 4; q++) wb[q] = W[(size_t)tis[q] * DD + d];

    for (int jb = 0; jb < jn; jb += 4) {
        float wn[4] = {0.f, 0.f, 0.f, 0.f};
        if (jb + 4 < jn) {
#pragma unroll
            for (int q = 0; q < 4; q++) wn[q] = W[(size_t)tis[jb + 4 + q] * DD + d];
        }
#pragma unroll
        for (int q = 0; q < 4; q++) {
            float tj = ts[jb + q];
            while (ptr < r1 && g_thr[sb + ptr] <= tj) {
                float a1 = g_es1[sb + ptr], a2 = g_es2[sb + ptr];
                int si = g_si[sb + ptr];
                float den = a1 * (C1 - c1) + a2 * c2;
                float v = __fdividef(a1 * (T1 - p1) + a2 * p2, den);
                v = (v > 0.f) ? v : (__expf(v) - 1.f);
                if (act) G[(size_t)si * DD + d] = v;
                ptr++;
            }
            float e1 = e1s[jb + q], e2 = e2s[jb + q];
            p1 += e1 * wb[q]; p2 += e2 * wb[q];
            c1 += e1; c2 += e2;
        }
#pragma unroll
        for (int q = 0; q < 4; q++) wb[q] = wn[q];
    }
    while (ptr < r1) {
        float a1 = g_es1[sb + ptr], a2 = g_es2[sb + ptr];
        int si = g_si[sb + ptr];
        float den = a1 * (C1 - c1) + a2 * c2;
        float v = __fdividef(a1 * (T1 - p1) + a2 * p2, den);
        v = (v > 0.f) ? v : (__expf(v) - 1.f);
        if (act) G[(size_t)si * DD + d] = v;
        ptr++;
    }
}

// ---------------- softmax + weighted sum ----------------
__global__ void softsum_kernel(const float* __restrict__ X, const float* __restrict__ sc,
                               int S, int slotM, float* __restrict__ outB) {
    __shared__ float wsm[64];
    int b = blockIdx.x, slot = blockIdx.y;
    int rowBase = slot * slotM + b * S;
    int lane = threadIdx.x;
    if (threadIdx.x < 32) {
        float v0 = (lane < S) ? sc[rowBase + lane] : -1e30f;
        float v1 = ((lane + 32) < S) ? sc[rowBase + lane + 32] : -1e30f;
        float m = fmaxf(v0, v1);
#pragma unroll
        for (int o = 16; o; o >>= 1) m = fmaxf(m, __shfl_xor_sync(0xffffffffu, m, o));
        float e0 = (lane < S) ? __expf(v0 - m) : 0.f;
        float e1 = ((lane + 32) < S) ? __expf(v1 - m) : 0.f;
        float sum = e0 + e1;
#pragma unroll
        for (int o = 16; o; o >>= 1) sum += __shfl_xor_sync(0xffffffffu, sum, o);
        float inv = 1.f / sum;
        wsm[lane] = e0 * inv;
        wsm[lane + 32] = e1 * inv;
    }
    __syncthreads();
    float* o = outB + (size_t)(slot * BB + b) * DD;
    for (int dd = threadIdx.x; dd < DD; dd += blockDim.x) {
        float acc = 0.f;
        for (int s = 0; s < S; s++)
            acc += wsm[s] * X[(size_t)(rowBase + s) * DD + dd];
        o[dd] = acc;
    }
}

// ---------------- reorder clicked encodings ----------------
__global__ void copy_uV_kernel() {
    int row  = blockIdx.x * 8 + (threadIdx.x >> 5);
    int lane = threadIdx.x & 31;
    if (row >= MUSER) return;
    int b = row / HH, j = row - b * HH;
    const float* src = d_enc + ((size_t)(CC + j) * BB + b) * DD;
    float* dst = d_uV + (size_t)row * DD;
    for (int c = lane; c < DD; c += 32) dst[c] = src[c];
}

// ---------------- final scores ----------------
__global__ void scores_kernel(float* __restrict__ out) {
    int w    = (blockIdx.x * blockDim.x + threadIdx.x) >> 5;
    int lane = threadIdx.x & 31;
    if (w >= BB * CC) return;
    int b = w / CC, c = w - b * CC;
    const float* cd = d_enc + ((size_t)c * BB + b) * DD;
    const float* u  = d_user + (size_t)b * DD;
    float acc = 0.f;
    for (int k = lane; k < DD; k += 32) acc += cd[k] * u[k];
#pragma unroll
    for (int o = 16; o; o >>= 1) acc += __shfl_xor_sync(0xffffffffu, acc, o);
    if (!lane) out[b * CC + c] = acc;
}

// ---------------- launch ----------------
extern "C" void kernel_launch(void* const* d_in, const int* in_sizes, int n_in,
                              void* d_out, int out_size) {
    const void* by200[4] = {0, 0, 0, 0};
    const void* by600[2] = {0, 0};
    const void* by60k[2] = {0, 0};
    const void* by90k[2] = {0, 0};
    const int* cand = 0; const int* clicked = 0; const float* emb = 0;
    int n200 = 0, n600 = 0, n60k = 0, n90k = 0;
    for (int i = 0; i < n_in; i++) {
        int sz = in_sizes[i];
        if      (sz == BB * CC * LL)      cand    = (const int*)d_in[i];
        else if (sz == BB * HH * LL)      clicked = (const int*)d_in[i];
        else if (sz == VV * DD)           emb     = (const float*)d_in[i];
        else if (sz == DD * DD  && n90k < 2) by90k[n90k++] = d_in[i];
        else if (sz == 2 * DD   && n600 < 2) by600[n600++] = d_in[i];
        else if (sz == QQ * DD  && n60k < 2) by60k[n60k++] = d_in[i];
        else if (sz == QQ       && n200 < 4) by200[n200++] = d_in[i];
    }
    const float* news_W     = (const float*)by90k[0];
    const float* user_W     = (const float*)by90k[1];
    const float* news_a     = (const float*)by600[0];
    const float* user_a     = (const float*)by600[1];
    const float* news_lin_w = (const float*)by60k[0];
    const float* user_lin_w = (const float*)by60k[1];
    const float* news_lin_b = (const float*)by200[0];
    const float* news_query = (const float*)by200[1];
    const float* user_lin_b = (const float*)by200[2];
    const float* user_query = (const float*)by200[3];
    float* out = (float*)d_out;

    float *pEmbW, *pVs, *pVt, *pV, *pWh, *pS, *pT, *pEnc;
    float *pUV, *pUWh, *pUS, *pUT, *pUG, *pUser;
    float *pScore, *pUScore, *pLwTn, *pLwTu;
    cudaGetSymbolAddress((void**)&pEmbW, d_embW);
    cudaGetSymbolAddress((void**)&pVs, d_vs);
    cudaGetSymbolAddress((void**)&pVt, d_vt);
    cudaGetSymbolAddress((void**)&pV, d_V);
    cudaGetSymbolAddress((void**)&pWh, d_Wh);
    cudaGetSymbolAddress((void**)&pS, d_sv);
    cudaGetSymbolAddress((void**)&pT, d_tv);
    cudaGetSymbolAddress((void**)&pEnc, d_enc);
    cudaGetSymbolAddress((void**)&pUV, d_uV);
    cudaGetSymbolAddress((void**)&pUWh, d_uWh);
    cudaGetSymbolAddress((void**)&pUS, d_us);
    cudaGetSymbolAddress((void**)&pUT, d_ut);
    cudaGetSymbolAddress((void**)&pUG, d_uG);
    cudaGetSymbolAddress((void**)&pUser, d_user);
    cudaGetSymbolAddress((void**)&pScore, g_score);
    cudaGetSymbolAddress((void**)&pUScore, g_uscore);
    cudaGetSymbolAddress((void**)&pLwTn, g_lwTn);
    cudaGetSymbolAddress((void**)&pLwTu, g_lwTu);

    const int NCH_NEWS = (MNEWS + JC - 1) / JC;   // 8
    const int NCH_USER = (MUSER + JC - 1) / JC;   // 13

    // prep
    init_kernel<<<(MTOT + 255) / 256, 256>>>();
    transpose_kernel<<<(DD * QQ + 255) / 256, 256>>>(news_lin_w, pLwTn);
    transpose_kernel<<<(DD * QQ + 255) / 256, 256>>>(user_lin_w, pLwTu);

    // news pipeline: vocab GEMM + vocab s,t, then per-slot contiguous gather
    gemm_kernel<<<dim3(3, (VV + 127) / 128), 256>>>(emb, news_W, pEmbW, VV);
    st_kernel<<<(VV + 7) / 8, 256>>>(pEmbW, news_a, pVs, pVt, VV);
    gatherWh_kernel<<<MTOT / 8, 256>>>(cand, clicked);
    sort_kernel<2048><<<NSLOT, 1024>>>(pT, pS, MNEWS, 0);
    partials_kernel<<<dim3(NCH_NEWS, NSLOT), 320>>>(pWh, (size_t)MNEWS * DD, MNEWS, 0);
    csweep_kernel<<<dim3(NCH_NEWS, NSLOT), 320>>>(pWh, (size_t)MNEWS * DD, pV, MNEWS, 0, NCH_NEWS);
    score_gemm_kernel<<<dim3(2, MTOT / 128), 256>>>(pV, pLwTn, news_lin_b, news_query, pScore);
    softsum_kernel<<<dim3(BB, NSLOT), 128>>>(pV, pScore, LL, MNEWS, pEnc);

    // user pipeline
    copy_uV_kernel<<<MUSER / 8, 256>>>();
    gemm_kernel<<<dim3(3, MUSER / 128), 256>>>(pUV, user_W, pUWh, MUSER);
    st_kernel<<<MUSER / 8, 256>>>(pUWh, user_a, pUS, pUT, MUSER);
    sort_kernel<4096><<<1, 1024>>>(pUT, pUS, MUSER, NSLOT);
    partials_kernel<<<dim3(NCH_USER, 1), 320>>>(pUWh, 0, MUSER, NSLOT);
    csweep_kernel<<<dim3(NCH_USER, 1), 320>>>(pUWh, 0, pUG, MUSER, NSLOT, NCH_USER);
    score_gemm_kernel<<<dim3(2, MUSER / 128), 256>>>(pUG, pLwTu, user_lin_b, user_query, pUScore);
    softsum_kernel<<<dim3(BB, 1), 128>>>(pUG, pUScore, HH, MUSER, pUser);

    scores_kernel<<<40, 256>>>(out);
}